// round 12
// baseline (speedup 1.0000x reference)
#include <cuda_runtime.h>
#include <mma.h>
#include <math.h>

using namespace nvcuda;

#define NTOK 64
#define HEADS 8
#define DH 32
#define DEPTH 2
#define DMODEL 256
#define MLPD 1024
#define NWIN 1024          // 4 * 16 * 16
#define MROWS (NWIN*NTOK)  // 65536
#define LN_EPS 1e-5f
#define ATT_SCALE 0.17677669529663687f   // 32^-0.5
#define OUT_ELEMS 16777216               // 4*256*128*128

// GEMM tiling
#define BM 128
#define BN 128
#define BK 16
// smem per stage: A 128x20 = 2560, B 16x132 = 2112 -> 4672; x2 stages = 9344
#define STAGE_F 4672
#define SMEM_F 9344

// weight scratch offsets (floats)
#define WOFF_PATCH 0
#define WOFF_QKV   65536            // + l*196608
#define WOFF_OUT   458752           // + l*65536
#define WOFF_W1    589824           // + l*262144
#define WOFF_W2    1114112          // + l*262144
#define WT_TOTAL   1638400

// ---------------- scratch (device globals; no allocation allowed) ----------
__device__ float g_gather[MROWS * DMODEL];
__device__ float g_t[MROWS * DMODEL];
__device__ float g_h[MROWS * DMODEL];
__device__ float g_qkv[MROWS * 3 * DMODEL];
__device__ float g_o[MROWS * DMODEL];
__device__ float g_mlp[MROWS * MLPD];
__device__ float g_add[DEPTH * HEADS * NTOK * NTOK];
__device__ float g_wt[WT_TOTAL];

// buffer ids: 0=g_gather 1=g_t 2=g_h 3=g_qkv 4=g_o 5=g_mlp
__device__ __forceinline__ float* buf(int id) {
    switch (id) {
        case 0: return g_gather;
        case 1: return g_t;
        case 2: return g_h;
        case 3: return g_qkv;
        case 4: return g_o;
        default: return g_mlp;
    }
}

__device__ __forceinline__ void cpa16(float* sdst, const float* gsrc) {
    unsigned saddr = (unsigned)__cvta_generic_to_shared(sdst);
    asm volatile("cp.async.ca.shared.global [%0], [%1], 16;" :: "r"(saddr), "l"(gsrc));
}

// ---------------- weight preconvert to tf32 --------------------------------
__global__ void wconv_kernel(const float* __restrict__ Wp, const float* __restrict__ Wq,
                             const float* __restrict__ Wo, const float* __restrict__ W1,
                             const float* __restrict__ W2) {
    int i = blockIdx.x * 256 + threadIdx.x;
    if (i >= WT_TOTAL) return;
    float v;
    if (i < WOFF_QKV)      v = Wp[i];
    else if (i < WOFF_OUT) v = Wq[i - WOFF_QKV];
    else if (i < WOFF_W1)  v = Wo[i - WOFF_OUT];
    else if (i < WOFF_W2)  v = W1[i - WOFF_W1];
    else                   v = W2[i - WOFF_W2];
    g_wt[i] = wmma::__float_to_tf32(v);
}

// ---------------- window gather (emits tf32-rounded: GEMM A operand) -------
__global__ void gather_kernel(const float* __restrict__ x) {
    int win = blockIdx.x;
    int b  = win >> 8;
    int wh = (win >> 4) & 15;
    int ww = win & 15;
    const float* xb = x + (size_t)b * 256 * 128 * 128;
    float* dst = g_gather + (size_t)win * NTOK * DMODEL;
    for (int idx = threadIdx.x; idx < NTOK * DMODEL; idx += blockDim.x) {
        int tok = idx >> 8;
        int c   = idx & 255;
        int y = tok >> 3, xx = tok & 7;
        int hh = wh * 8 + y, ww2 = ww * 8 + xx;
        dst[idx] = wmma::__float_to_tf32(xb[((size_t)c * 128 + hh) * 128 + ww2]);
    }
}

// ---------------- tf32 tensor-core GEMM, 128x128 tile, cp.async 2-stage ----
// A = buf(aid) [M,K] (already tf32-rounded), B = g_wt + boff [K,N] (tf32),
// C = buf(cid). 8 warps: grid 2(M) x 4(N), warp tile 64x32 (4x2 frags).
template<bool BIASF, bool RELU, bool RESID, bool CVT>
__global__ void __launch_bounds__(256)
gemm_tc(int aid, int boff, const float* __restrict__ bias,
        int cid, int M, int N, int K) {
    const float* __restrict__ A = buf(aid);
    const float* __restrict__ Bw = g_wt + boff;
    float* __restrict__ C = buf(cid);

    __shared__ float smem[SMEM_F];

    int tid = threadIdx.x;
    int w   = tid >> 5;
    int lane = tid & 31;
    int wr = w >> 2, wc = w & 3;               // 2 x 4 warp grid
    int m0 = blockIdx.y * BM;
    int n0 = blockIdx.x * BN;

    wmma::fragment<wmma::accumulator, 16, 16, 8, float> acc[4][2];
    #pragma unroll
    for (int i = 0; i < 4; i++)
        #pragma unroll
        for (int j = 0; j < 2; j++)
            wmma::fill_fragment(acc[i][j], 0.0f);

    // stage loader: A 128x16 (row-major, stride 20), B 16x128 (row-major, stride 132)
    auto load_stage = [&](int st, int kk) {
        float* as = smem + st * STAGE_F;
        float* bs = as + 2560;
        #pragma unroll
        for (int h = 0; h < 2; h++) {
            int c = tid + h * 256;             // 0..511
            int m = c >> 2, kq = (c & 3) << 2;
            cpa16(as + m * 20 + kq, A + (size_t)(m0 + m) * K + kk + kq);
            int k = c >> 5, nq = (c & 31) << 2;
            cpa16(bs + k * 132 + nq, Bw + (size_t)(kk + k) * N + n0 + nq);
        }
    };

    load_stage(0, 0);
    asm volatile("cp.async.commit_group;");

    int s = 0;
    for (int k0 = 0; k0 < K; k0 += BK) {
        if (k0 + BK < K) {
            load_stage(s ^ 1, k0 + BK);
            asm volatile("cp.async.commit_group;");
            asm volatile("cp.async.wait_group 1;");
        } else {
            asm volatile("cp.async.wait_group 0;");
        }
        __syncthreads();
        float* as = smem + s * STAGE_F;
        float* bs = as + 2560;
        #pragma unroll
        for (int ks = 0; ks < 2; ks++) {
            wmma::fragment<wmma::matrix_a, 16, 16, 8, wmma::precision::tf32, wmma::row_major> af[4];
            wmma::fragment<wmma::matrix_b, 16, 16, 8, wmma::precision::tf32, wmma::row_major> bf[2];
            #pragma unroll
            for (int i = 0; i < 4; i++)
                wmma::load_matrix_sync(af[i], as + (wr * 64 + i * 16) * 20 + ks * 8, 20);
            #pragma unroll
            for (int j = 0; j < 2; j++)
                wmma::load_matrix_sync(bf[j], bs + (ks * 8) * 132 + wc * 32 + j * 16, 132);
            #pragma unroll
            for (int i = 0; i < 4; i++)
                #pragma unroll
                for (int j = 0; j < 2; j++)
                    wmma::mma_sync(acc[i][j], af[i], bf[j], acc[i][j]);
        }
        __syncthreads();
        s ^= 1;
    }

    // epilogue: two waves, 4 warps each stage 64x36 into smem then coalesced write
    int ncol = n0 + wc * 32 + lane;
    float bv = BIASF ? bias[ncol] : 0.0f;
    #pragma unroll
    for (int wave = 0; wave < 2; wave++) {
        __syncthreads();
        if (wr == wave) {
            float* cw = smem + (w & 3) * 2304;
            #pragma unroll
            for (int i = 0; i < 4; i++)
                #pragma unroll
                for (int j = 0; j < 2; j++)
                    wmma::store_matrix_sync(cw + (i * 16) * 36 + j * 16, acc[i][j], 36,
                                            wmma::mem_row_major);
            __syncwarp();
            #pragma unroll 4
            for (int r = 0; r < 64; r++) {
                int m = m0 + wr * 64 + r;
                float v = cw[r * 36 + lane];
                if (BIASF) v += bv;
                if (RELU)  v = fmaxf(v, 0.f);
                if (RESID) v += g_t[(size_t)m * N + ncol];
                if (CVT)   v = wmma::__float_to_tf32(v);
                C[(size_t)m * N + ncol] = v;
            }
        }
    }
}

// ---------------- LayerNorm (256): g_t -> g_h (tf32-rounded) ---------------
__global__ void ln_kernel(const float* __restrict__ g, const float* __restrict__ b) {
    int row  = blockIdx.x * 8 + (threadIdx.x >> 5);
    int lane = threadIdx.x & 31;
    const float* p = g_t + (size_t)row * DMODEL;
    float v[8];
    float s = 0.f;
    #pragma unroll
    for (int i = 0; i < 8; i++) { v[i] = p[lane + i * 32]; s += v[i]; }
    #pragma unroll
    for (int o = 16; o; o >>= 1) s += __shfl_xor_sync(0xffffffffu, s, o);
    float mean = s * (1.f / 256.f);
    float vs = 0.f;
    #pragma unroll
    for (int i = 0; i < 8; i++) { float d = v[i] - mean; vs += d * d; }
    #pragma unroll
    for (int o = 16; o; o >>= 1) vs += __shfl_xor_sync(0xffffffffu, vs, o);
    float r = rsqrtf(vs * (1.f / 256.f) + LN_EPS);
    float* q = g_h + (size_t)row * DMODEL;
    #pragma unroll
    for (int i = 0; i < 8; i++) {
        int col = lane + i * 32;
        q[col] = wmma::__float_to_tf32((v[i] - mean) * r * g[col] + b[col]);
    }
}

// ---------------- precompute bias + 0.01 * gaussian decay ------------------
__global__ void addmat_kernel(const float* __restrict__ bias_table,
                              const float* __restrict__ headsita) {
    int idx = blockIdx.x * blockDim.x + threadIdx.x;
    if (idx >= DEPTH * HEADS * NTOK * NTOK) return;
    int j = idx & 63, i = (idx >> 6) & 63, head = (idx >> 12) & 7, l = idx >> 15;
    int yi = i >> 3, xi = i & 7, yj = j >> 3, xj = j & 7;
    int dy = yi - yj, dx = xi - xj;
    int tbl = (dy + 7) * 15 + (dx + 7);
    float bias = bias_table[(l * 225 + tbl) * 8 + head];
    float sita = headsita[l * 8 + head];
    float factor = 1.0f / (2.0f * sita * sita + 1e-10f);
    float fy = (float)dy * 0.125f, fx = (float)dx * 0.125f;
    float dis = fy * fy + fx * fx;
    g_add[idx] = bias + 0.01f * expf(-factor * dis);
}

// ---------------- fused windowed attention per (window, head) --------------
__global__ void attn_kernel(float* __restrict__ attns_out, int layer) {
    int win  = blockIdx.x >> 3;
    int head = blockIdx.x & 7;
    __shared__ float qs[64][33], ks[64][33], vs_[64][33];
    __shared__ float ds[64][65];
    int tid = threadIdx.x;
    int warp = tid >> 5, lane = tid & 31;
    const float* base = g_qkv + (size_t)win * 64 * 768 + head * 32;
    for (int tok = warp; tok < 64; tok += 8) {
        qs[tok][lane]  = base[tok * 768 + lane];
        ks[tok][lane]  = base[tok * 768 + 256 + lane];
        vs_[tok][lane] = base[tok * 768 + 512 + lane];
    }
    __syncthreads();
    // QK^T with 4x4 register tiling
    {
        int ty = tid >> 4, tx = tid & 15;
        int i0 = ty * 4, j0 = tx * 4;
        float acc[4][4] = {};
        #pragma unroll 8
        for (int d = 0; d < 32; d++) {
            float qv[4], kv[4];
            #pragma unroll
            for (int r = 0; r < 4; r++) qv[r] = qs[i0 + r][d];
            #pragma unroll
            for (int c = 0; c < 4; c++) kv[c] = ks[j0 + c][d];
            #pragma unroll
            for (int r = 0; r < 4; r++)
                #pragma unroll
                for (int c = 0; c < 4; c++)
                    acc[r][c] += qv[r] * kv[c];
        }
        #pragma unroll
        for (int r = 0; r < 4; r++)
            #pragma unroll
            for (int c = 0; c < 4; c++)
                ds[i0 + r][j0 + c] = acc[r][c] * ATT_SCALE;
    }
    __syncthreads();
    const float* addb = g_add + ((size_t)(layer * 8 + head)) * 4096;
    float* a_out = attns_out + (((size_t)layer * NWIN + win) * 8 + head) * 4096;
    for (int i = warp; i < 64; i += 8) {
        float x0 = ds[i][lane], x1 = ds[i][lane + 32];
        float m = fmaxf(x0, x1);
        #pragma unroll
        for (int sh = 16; sh; sh >>= 1) m = fmaxf(m, __shfl_xor_sync(0xffffffffu, m, sh));
        float e0 = __expf(x0 - m), e1 = __expf(x1 - m);
        float s = e0 + e1;
        #pragma unroll
        for (int sh = 16; sh; sh >>= 1) s += __shfl_xor_sync(0xffffffffu, s, sh);
        float inv = 1.f / s;
        a_out[i * 64 + lane]      = e0 * inv;
        a_out[i * 64 + lane + 32] = e1 * inv;
        float y0 = x0 + addb[i * 64 + lane];
        float y1 = x1 + addb[i * 64 + lane + 32];
        float m2 = fmaxf(y0, y1);
        #pragma unroll
        for (int sh = 16; sh; sh >>= 1) m2 = fmaxf(m2, __shfl_xor_sync(0xffffffffu, m2, sh));
        float f0 = __expf(y0 - m2), f1 = __expf(y1 - m2);
        float s2 = f0 + f1;
        #pragma unroll
        for (int sh = 16; sh; sh >>= 1) s2 += __shfl_xor_sync(0xffffffffu, s2, sh);
        float inv2 = 1.f / s2;
        ds[i][lane]      = f0 * inv2;
        ds[i][lane + 32] = f1 * inv2;
    }
    __syncthreads();
    // P @ V with 4x2 register tiling; output tf32-rounded (GEMM A operand)
    {
        int ty = tid >> 4, tx = tid & 15;
        int i0 = ty * 4, d0 = tx * 2;
        float acc[4][2] = {};
        #pragma unroll 8
        for (int j = 0; j < 64; j++) {
            float dv[4], vv[2];
            #pragma unroll
            for (int r = 0; r < 4; r++) dv[r] = ds[i0 + r][j];
            #pragma unroll
            for (int c = 0; c < 2; c++) vv[c] = vs_[j][d0 + c];
            #pragma unroll
            for (int r = 0; r < 4; r++)
                #pragma unroll
                for (int c = 0; c < 2; c++)
                    acc[r][c] += dv[r] * vv[c];
        }
        float* ob = g_o + (size_t)win * 64 * 256 + head * 32;
        #pragma unroll
        for (int r = 0; r < 4; r++)
            #pragma unroll
            for (int c = 0; c < 2; c++)
                ob[(i0 + r) * 256 + d0 + c] = wmma::__float_to_tf32(acc[r][c]);
    }
}

// ---------------- window reverse: g_t -> out[B,D,H,W] ----------------------
__global__ void unpermute_kernel(float* __restrict__ out) {
    int idx = blockIdx.x * 256 + threadIdx.x;
    int w = idx & 127, h2 = (idx >> 7) & 127, d = (idx >> 14) & 255, b = idx >> 22;
    int win = (b * 16 + (h2 >> 3)) * 16 + (w >> 3);
    int tok = (h2 & 7) * 8 + (w & 7);
    out[idx] = g_t[((size_t)win * 64 + tok) * 256 + d];
}

// ---------------------------------------------------------------------------
extern "C" void kernel_launch(void* const* d_in, const int* in_sizes, int n_in,
                              void* d_out, int out_size) {
    const float* x          = (const float*)d_in[0];
    const float* W_patch    = (const float*)d_in[1];
    const float* b_patch    = (const float*)d_in[2];
    const float* ln1_g      = (const float*)d_in[3];
    const float* ln1_b      = (const float*)d_in[4];
    const float* Wqkv       = (const float*)d_in[5];
    const float* headsita   = (const float*)d_in[6];
    const float* bias_table = (const float*)d_in[7];
    const float* Wout       = (const float*)d_in[8];
    const float* bout       = (const float*)d_in[9];
    const float* ln2_g      = (const float*)d_in[10];
    const float* ln2_b      = (const float*)d_in[11];
    const float* W1         = (const float*)d_in[12];
    const float* b1         = (const float*)d_in[13];
    const float* W2         = (const float*)d_in[14];
    const float* b2         = (const float*)d_in[15];

    float* out   = (float*)d_out;
    float* attns = out + OUT_ELEMS;

    wconv_kernel<<<(WT_TOTAL + 255) / 256, 256>>>(W_patch, Wqkv, Wout, W1, W2);
    addmat_kernel<<<256, 256>>>(bias_table, headsita);
    gather_kernel<<<NWIN, 256>>>(x);
    // patch embed: g_t = g_gather @ W_patch + b_patch
    gemm_tc<true, false, false, false><<<dim3(DMODEL / BN, MROWS / BM), 256>>>(
        0, WOFF_PATCH, b_patch, 1, MROWS, DMODEL, DMODEL);

    for (int l = 0; l < DEPTH; l++) {
        ln_kernel<<<MROWS / 8, 256>>>(ln1_g + l * DMODEL, ln1_b + l * DMODEL);
        // g_qkv = g_h @ Wqkv[l]   (fp32 output for attention)
        gemm_tc<false, false, false, false><<<dim3(768 / BN, MROWS / BM), 256>>>(
            2, WOFF_QKV + l * 196608, (const float*)0, 3, MROWS, 768, DMODEL);
        attn_kernel<<<NWIN * HEADS, 256>>>(attns, l);
        // g_t = g_o @ Wout[l] + bout[l] + g_t
        gemm_tc<true, false, true, false><<<dim3(DMODEL / BN, MROWS / BM), 256>>>(
            4, WOFF_OUT + l * 65536, bout + l * DMODEL, 1, MROWS, DMODEL, DMODEL);
        ln_kernel<<<MROWS / 8, 256>>>(ln2_g + l * DMODEL, ln2_b + l * DMODEL);
        // g_mlp = relu(g_h @ W1[l] + b1[l])  (tf32-rounded: feeds next GEMM as A)
        gemm_tc<true, true, false, true><<<dim3(MLPD / BN, MROWS / BM), 256>>>(
            2, WOFF_W1 + l * 262144, b1 + l * MLPD, 5, MROWS, MLPD, DMODEL);
        // g_t = g_mlp @ W2[l] + b2[l] + g_t
        gemm_tc<true, false, true, false><<<dim3(DMODEL / BN, MROWS / BM), 256>>>(
            5, WOFF_W2 + l * 262144, b2 + l * DMODEL, 1, MROWS, DMODEL, MLPD);
    }

    unpermute_kernel<<<OUT_ELEMS / 256, 256>>>(out);
}

// round 16
// speedup vs baseline: 1.2802x; 1.2802x over previous
#include <cuda_runtime.h>
#include <mma.h>
#include <math.h>

using namespace nvcuda;

#define NTOK 64
#define HEADS 8
#define DH 32
#define DEPTH 2
#define DMODEL 256
#define MLPD 1024
#define NWIN 1024          // 4 * 16 * 16
#define MROWS (NWIN*NTOK)  // 65536
#define LN_EPS 1e-5f
#define ATT_SCALE 0.17677669529663687f   // 32^-0.5
#define OUT_ELEMS 16777216               // 4*256*128*128

// GEMM tiling
#define BM 128
#define BN 128
#define BK 32
// per stage: A 128x36 = 4608, B 32x132 = 4224 -> 8832 floats; 2 stages = 17664
#define STAGE_F 8832
#define SMEM_F 17664
#define SMEM_BYTES (SMEM_F * 4)

// weight scratch offsets (floats)
#define WOFF_PATCH 0
#define WOFF_QKV   65536            // + l*196608
#define WOFF_OUT   458752           // + l*65536
#define WOFF_W1    589824           // + l*262144
#define WOFF_W2    1114112          // + l*262144
#define WT_TOTAL   1638400

// ---------------- scratch (device globals; no allocation allowed) ----------
__device__ float g_gather[MROWS * DMODEL];
__device__ float g_t[MROWS * DMODEL];
__device__ float g_h[MROWS * DMODEL];
__device__ float g_qkv[MROWS * 3 * DMODEL];
__device__ float g_o[MROWS * DMODEL];
__device__ float g_mlp[MROWS * MLPD];
__device__ float g_add[DEPTH * HEADS * NTOK * NTOK];
__device__ float g_wt[WT_TOTAL];

// buffer ids: 0=g_gather 1=g_t 2=g_h 3=g_qkv 4=g_o 5=g_mlp
__device__ __forceinline__ float* buf(int id) {
    switch (id) {
        case 0: return g_gather;
        case 1: return g_t;
        case 2: return g_h;
        case 3: return g_qkv;
        case 4: return g_o;
        default: return g_mlp;
    }
}

__device__ __forceinline__ void cpa16(float* sdst, const float* gsrc) {
    unsigned saddr = (unsigned)__cvta_generic_to_shared(sdst);
    asm volatile("cp.async.ca.shared.global [%0], [%1], 16;" :: "r"(saddr), "l"(gsrc));
}

// ---------------- weight preconvert to tf32 --------------------------------
__global__ void wconv_kernel(const float* __restrict__ Wp, const float* __restrict__ Wq,
                             const float* __restrict__ Wo, const float* __restrict__ W1,
                             const float* __restrict__ W2) {
    int i = blockIdx.x * 256 + threadIdx.x;
    if (i >= WT_TOTAL) return;
    float v;
    if (i < WOFF_QKV)      v = Wp[i];
    else if (i < WOFF_OUT) v = Wq[i - WOFF_QKV];
    else if (i < WOFF_W1)  v = Wo[i - WOFF_OUT];
    else if (i < WOFF_W2)  v = W1[i - WOFF_W1];
    else                   v = W2[i - WOFF_W2];
    g_wt[i] = wmma::__float_to_tf32(v);
}

// ---------------- window gather (emits tf32-rounded: GEMM A operand) -------
__global__ void gather_kernel(const float* __restrict__ x) {
    int win = blockIdx.x;
    int b  = win >> 8;
    int wh = (win >> 4) & 15;
    int ww = win & 15;
    const float* xb = x + (size_t)b * 256 * 128 * 128;
    float* dst = g_gather + (size_t)win * NTOK * DMODEL;
    for (int idx = threadIdx.x; idx < NTOK * DMODEL; idx += blockDim.x) {
        int tok = idx >> 8;
        int c   = idx & 255;
        int y = tok >> 3, xx = tok & 7;
        int hh = wh * 8 + y, ww2 = ww * 8 + xx;
        dst[idx] = wmma::__float_to_tf32(xb[((size_t)c * 128 + hh) * 128 + ww2]);
    }
}

// ---------------- tf32 tensor-core GEMM, 128x128 tile, 1 sync per slab -----
// A = buf(aid) [M,K] (tf32-rounded), B = g_wt + boff [K,N] (tf32), C = buf(cid).
// 8 warps: grid 2(M) x 4(N), warp tile 64x32 (4x2 frags). Dynamic smem.
template<bool BIASF, bool RELU, bool RESID, bool CVT>
__global__ void __launch_bounds__(256, 2)
gemm_tc(int aid, int boff, const float* __restrict__ bias,
        int cid, int M, int N, int K) {
    const float* __restrict__ A = buf(aid);
    const float* __restrict__ Bw = g_wt + boff;
    float* __restrict__ C = buf(cid);

    extern __shared__ float smem[];

    int tid = threadIdx.x;
    int w   = tid >> 5;
    int lane = tid & 31;
    int wr = w >> 2, wc = w & 3;               // 2 x 4 warp grid
    int m0 = blockIdx.y * BM;
    int n0 = blockIdx.x * BN;

    wmma::fragment<wmma::accumulator, 16, 16, 8, float> acc[4][2];
    #pragma unroll
    for (int i = 0; i < 4; i++)
        #pragma unroll
        for (int j = 0; j < 2; j++)
            wmma::fill_fragment(acc[i][j], 0.0f);

    // stage: A 128x32 (stride 36), B 32x128 (stride 132)
    auto load_stage = [&](int st, int kk) {
        float* as = smem + st * STAGE_F;
        float* bs = as + 4608;
        #pragma unroll
        for (int h = 0; h < 4; h++) {
            int c = tid + h * 256;             // 0..1023
            int m = c >> 3, kq = (c & 7) << 2;
            cpa16(as + m * 36 + kq, A + (size_t)(m0 + m) * K + kk + kq);
            int k = c >> 5, nq = (c & 31) << 2;
            cpa16(bs + k * 132 + nq, Bw + (size_t)(kk + k) * N + n0 + nq);
        }
    };

    load_stage(0, 0);
    asm volatile("cp.async.commit_group;");

    int s = 0;
    for (int k0 = 0; k0 < K; k0 += BK) {
        asm volatile("cp.async.wait_group 0;");
        __syncthreads();
        // issue next stage; safe: the sync above proves stage s^1 is no longer read
        if (k0 + BK < K) {
            load_stage(s ^ 1, k0 + BK);
            asm volatile("cp.async.commit_group;");
        }
        float* as = smem + s * STAGE_F;
        float* bs = as + 4608;
        #pragma unroll
        for (int ks = 0; ks < 4; ks++) {
            wmma::fragment<wmma::matrix_a, 16, 16, 8, wmma::precision::tf32, wmma::row_major> af[4];
            wmma::fragment<wmma::matrix_b, 16, 16, 8, wmma::precision::tf32, wmma::row_major> bf[2];
            #pragma unroll
            for (int i = 0; i < 4; i++)
                wmma::load_matrix_sync(af[i], as + (wr * 64 + i * 16) * 36 + ks * 8, 36);
            #pragma unroll
            for (int j = 0; j < 2; j++)
                wmma::load_matrix_sync(bf[j], bs + (ks * 8) * 132 + wc * 32 + j * 16, 132);
            #pragma unroll
            for (int i = 0; i < 4; i++)
                #pragma unroll
                for (int j = 0; j < 2; j++)
                    wmma::mma_sync(acc[i][j], af[i], bf[j], acc[i][j]);
        }
        s ^= 1;
    }

    // single-pass epilogue: stage full 128x132 tile, then coalesced writes
    __syncthreads();
    #pragma unroll
    for (int i = 0; i < 4; i++)
        #pragma unroll
        for (int j = 0; j < 2; j++)
            wmma::store_matrix_sync(smem + (wr * 64 + i * 16) * 132 + wc * 32 + j * 16,
                                    acc[i][j], 132, wmma::mem_row_major);
    __syncthreads();

    int col = lane * 4;
    float4 bv = BIASF ? *(const float4*)(bias + n0 + col) : make_float4(0.f, 0.f, 0.f, 0.f);
    #pragma unroll 4
    for (int rr = 0; rr < 16; rr++) {
        int r = w * 16 + rr;
        int m = m0 + r;
        float4 v = *(float4*)(smem + r * 132 + col);
        if (BIASF) { v.x += bv.x; v.y += bv.y; v.z += bv.z; v.w += bv.w; }
        if (RELU)  { v.x = fmaxf(v.x, 0.f); v.y = fmaxf(v.y, 0.f);
                     v.z = fmaxf(v.z, 0.f); v.w = fmaxf(v.w, 0.f); }
        if (RESID) {
            float4 rv = *(const float4*)(g_t + (size_t)m * N + n0 + col);
            v.x += rv.x; v.y += rv.y; v.z += rv.z; v.w += rv.w;
        }
        if (CVT) {
            v.x = wmma::__float_to_tf32(v.x); v.y = wmma::__float_to_tf32(v.y);
            v.z = wmma::__float_to_tf32(v.z); v.w = wmma::__float_to_tf32(v.w);
        }
        *(float4*)(C + (size_t)m * N + n0 + col) = v;
    }
}

// ---------------- LayerNorm (256): g_t -> g_h (tf32-rounded) ---------------
__global__ void ln_kernel(const float* __restrict__ g, const float* __restrict__ b) {
    int row  = blockIdx.x * 8 + (threadIdx.x >> 5);
    int lane = threadIdx.x & 31;
    const float* p = g_t + (size_t)row * DMODEL;
    float v[8];
    float s = 0.f;
    #pragma unroll
    for (int i = 0; i < 8; i++) { v[i] = p[lane + i * 32]; s += v[i]; }
    #pragma unroll
    for (int o = 16; o; o >>= 1) s += __shfl_xor_sync(0xffffffffu, s, o);
    float mean = s * (1.f / 256.f);
    float vs = 0.f;
    #pragma unroll
    for (int i = 0; i < 8; i++) { float d = v[i] - mean; vs += d * d; }
    #pragma unroll
    for (int o = 16; o; o >>= 1) vs += __shfl_xor_sync(0xffffffffu, vs, o);
    float r = rsqrtf(vs * (1.f / 256.f) + LN_EPS);
    float* q = g_h + (size_t)row * DMODEL;
    #pragma unroll
    for (int i = 0; i < 8; i++) {
        int col = lane + i * 32;
        q[col] = wmma::__float_to_tf32((v[i] - mean) * r * g[col] + b[col]);
    }
}

// ---------------- precompute bias + 0.01 * gaussian decay ------------------
__global__ void addmat_kernel(const float* __restrict__ bias_table,
                              const float* __restrict__ headsita) {
    int idx = blockIdx.x * blockDim.x + threadIdx.x;
    if (idx >= DEPTH * HEADS * NTOK * NTOK) return;
    int j = idx & 63, i = (idx >> 6) & 63, head = (idx >> 12) & 7, l = idx >> 15;
    int yi = i >> 3, xi = i & 7, yj = j >> 3, xj = j & 7;
    int dy = yi - yj, dx = xi - xj;
    int tbl = (dy + 7) * 15 + (dx + 7);
    float bias = bias_table[(l * 225 + tbl) * 8 + head];
    float sita = headsita[l * 8 + head];
    float factor = 1.0f / (2.0f * sita * sita + 1e-10f);
    float fy = (float)dy * 0.125f, fx = (float)dx * 0.125f;
    float dis = fy * fy + fx * fx;
    g_add[idx] = bias + 0.01f * expf(-factor * dis);
}

// ---------------- fused windowed attention per (window, head) --------------
__global__ void attn_kernel(float* __restrict__ attns_out, int layer) {
    int win  = blockIdx.x >> 3;
    int head = blockIdx.x & 7;
    __shared__ float qs[64][33], ks[64][33], vs_[64][33];
    __shared__ float ds[64][65];
    int tid = threadIdx.x;
    int warp = tid >> 5, lane = tid & 31;
    const float* base = g_qkv + (size_t)win * 64 * 768 + head * 32;
    for (int tok = warp; tok < 64; tok += 8) {
        qs[tok][lane]  = base[tok * 768 + lane];
        ks[tok][lane]  = base[tok * 768 + 256 + lane];
        vs_[tok][lane] = base[tok * 768 + 512 + lane];
    }
    __syncthreads();
    // QK^T with 4x4 register tiling
    {
        int ty = tid >> 4, tx = tid & 15;
        int i0 = ty * 4, j0 = tx * 4;
        float acc[4][4] = {};
        #pragma unroll 8
        for (int d = 0; d < 32; d++) {
            float qv[4], kv[4];
            #pragma unroll
            for (int r = 0; r < 4; r++) qv[r] = qs[i0 + r][d];
            #pragma unroll
            for (int c = 0; c < 4; c++) kv[c] = ks[j0 + c][d];
            #pragma unroll
            for (int r = 0; r < 4; r++)
                #pragma unroll
                for (int c = 0; c < 4; c++)
                    acc[r][c] += qv[r] * kv[c];
        }
        #pragma unroll
        for (int r = 0; r < 4; r++)
            #pragma unroll
            for (int c = 0; c < 4; c++)
                ds[i0 + r][j0 + c] = acc[r][c] * ATT_SCALE;
    }
    __syncthreads();
    const float* addb = g_add + ((size_t)(layer * 8 + head)) * 4096;
    float* a_out = attns_out + (((size_t)layer * NWIN + win) * 8 + head) * 4096;
    for (int i = warp; i < 64; i += 8) {
        float x0 = ds[i][lane], x1 = ds[i][lane + 32];
        float m = fmaxf(x0, x1);
        #pragma unroll
        for (int sh = 16; sh; sh >>= 1) m = fmaxf(m, __shfl_xor_sync(0xffffffffu, m, sh));
        float e0 = __expf(x0 - m), e1 = __expf(x1 - m);
        float s = e0 + e1;
        #pragma unroll
        for (int sh = 16; sh; sh >>= 1) s += __shfl_xor_sync(0xffffffffu, s, sh);
        float inv = 1.f / s;
        a_out[i * 64 + lane]      = e0 * inv;
        a_out[i * 64 + lane + 32] = e1 * inv;
        float y0 = x0 + addb[i * 64 + lane];
        float y1 = x1 + addb[i * 64 + lane + 32];
        float m2 = fmaxf(y0, y1);
        #pragma unroll
        for (int sh = 16; sh; sh >>= 1) m2 = fmaxf(m2, __shfl_xor_sync(0xffffffffu, m2, sh));
        float f0 = __expf(y0 - m2), f1 = __expf(y1 - m2);
        float s2 = f0 + f1;
        #pragma unroll
        for (int sh = 16; sh; sh >>= 1) s2 += __shfl_xor_sync(0xffffffffu, s2, sh);
        float inv2 = 1.f / s2;
        ds[i][lane]      = f0 * inv2;
        ds[i][lane + 32] = f1 * inv2;
    }
    __syncthreads();
    // P @ V with 4x2 register tiling; output tf32-rounded (GEMM A operand)
    {
        int ty = tid >> 4, tx = tid & 15;
        int i0 = ty * 4, d0 = tx * 2;
        float acc[4][2] = {};
        #pragma unroll 8
        for (int j = 0; j < 64; j++) {
            float dv[4], vv[2];
            #pragma unroll
            for (int r = 0; r < 4; r++) dv[r] = ds[i0 + r][j];
            #pragma unroll
            for (int c = 0; c < 2; c++) vv[c] = vs_[j][d0 + c];
            #pragma unroll
            for (int r = 0; r < 4; r++)
                #pragma unroll
                for (int c = 0; c < 2; c++)
                    acc[r][c] += dv[r] * vv[c];
        }
        float* ob = g_o + (size_t)win * 64 * 256 + head * 32;
        #pragma unroll
        for (int r = 0; r < 4; r++)
            #pragma unroll
            for (int c = 0; c < 2; c++)
                ob[(i0 + r) * 256 + d0 + c] = wmma::__float_to_tf32(acc[r][c]);
    }
}

// ---------------- window reverse: g_t -> out[B,D,H,W] ----------------------
__global__ void unpermute_kernel(float* __restrict__ out) {
    int idx = blockIdx.x * 256 + threadIdx.x;
    int w = idx & 127, h2 = (idx >> 7) & 127, d = (idx >> 14) & 255, b = idx >> 22;
    int win = (b * 16 + (h2 >> 3)) * 16 + (w >> 3);
    int tok = (h2 & 7) * 8 + (w & 7);
    out[idx] = g_t[((size_t)win * 64 + tok) * 256 + d];
}

// ---------------------------------------------------------------------------
extern "C" void kernel_launch(void* const* d_in, const int* in_sizes, int n_in,
                              void* d_out, int out_size) {
    const float* x          = (const float*)d_in[0];
    const float* W_patch    = (const float*)d_in[1];
    const float* b_patch    = (const float*)d_in[2];
    const float* ln1_g      = (const float*)d_in[3];
    const float* ln1_b      = (const float*)d_in[4];
    const float* Wqkv       = (const float*)d_in[5];
    const float* headsita   = (const float*)d_in[6];
    const float* bias_table = (const float*)d_in[7];
    const float* Wout       = (const float*)d_in[8];
    const float* bout       = (const float*)d_in[9];
    const float* ln2_g      = (const float*)d_in[10];
    const float* ln2_b      = (const float*)d_in[11];
    const float* W1         = (const float*)d_in[12];
    const float* b1         = (const float*)d_in[13];
    const float* W2         = (const float*)d_in[14];
    const float* b2         = (const float*)d_in[15];

    float* out   = (float*)d_out;
    float* attns = out + OUT_ELEMS;

    // opt in to 69KB dynamic smem (idempotent; not a stream op)
    cudaFuncSetAttribute((const void*)gemm_tc<true,  false, false, false>,
                         cudaFuncAttributeMaxDynamicSharedMemorySize, SMEM_BYTES);
    cudaFuncSetAttribute((const void*)gemm_tc<false, false, false, false>,
                         cudaFuncAttributeMaxDynamicSharedMemorySize, SMEM_BYTES);
    cudaFuncSetAttribute((const void*)gemm_tc<true,  false, true,  false>,
                         cudaFuncAttributeMaxDynamicSharedMemorySize, SMEM_BYTES);
    cudaFuncSetAttribute((const void*)gemm_tc<true,  true,  false, true>,
                         cudaFuncAttributeMaxDynamicSharedMemorySize, SMEM_BYTES);

    wconv_kernel<<<(WT_TOTAL + 255) / 256, 256>>>(W_patch, Wqkv, Wout, W1, W2);
    addmat_kernel<<<256, 256>>>(bias_table, headsita);
    gather_kernel<<<NWIN, 256>>>(x);
    // patch embed: g_t = g_gather @ W_patch + b_patch
    gemm_tc<true, false, false, false><<<dim3(DMODEL / BN, MROWS / BM), 256, SMEM_BYTES>>>(
        0, WOFF_PATCH, b_patch, 1, MROWS, DMODEL, DMODEL);

    for (int l = 0; l < DEPTH; l++) {
        ln_kernel<<<MROWS / 8, 256>>>(ln1_g + l * DMODEL, ln1_b + l * DMODEL);
        // g_qkv = g_h @ Wqkv[l]   (fp32 output for attention)
        gemm_tc<false, false, false, false><<<dim3(768 / BN, MROWS / BM), 256, SMEM_BYTES>>>(
            2, WOFF_QKV + l * 196608, (const float*)0, 3, MROWS, 768, DMODEL);
        attn_kernel<<<NWIN * HEADS, 256>>>(attns, l);
        // g_t = g_o @ Wout[l] + bout[l] + g_t
        gemm_tc<true, false, true, false><<<dim3(DMODEL / BN, MROWS / BM), 256, SMEM_BYTES>>>(
            4, WOFF_OUT + l * 65536, bout + l * DMODEL, 1, MROWS, DMODEL, DMODEL);
        ln_kernel<<<MROWS / 8, 256>>>(ln2_g + l * DMODEL, ln2_b + l * DMODEL);
        // g_mlp = relu(g_h @ W1[l] + b1[l])  (tf32-rounded: feeds next GEMM as A)
        gemm_tc<true, true, false, true><<<dim3(MLPD / BN, MROWS / BM), 256, SMEM_BYTES>>>(
            2, WOFF_W1 + l * 262144, b1 + l * MLPD, 5, MROWS, MLPD, DMODEL);
        // g_t = g_mlp @ W2[l] + b2[l] + g_t
        gemm_tc<true, false, true, false><<<dim3(DMODEL / BN, MROWS / BM), 256, SMEM_BYTES>>>(
            5, WOFF_W2 + l * 262144, b2 + l * DMODEL, 1, MROWS, DMODEL, MLPD);
    }

    unpermute_kernel<<<OUT_ELEMS / 256, 256>>>(out);
}